// round 16
// baseline (speedup 1.0000x reference)
#include <cuda_runtime.h>
#include <cuda_fp16.h>
#include <cstdint>

#define NN    100000
#define EE    1600000
#define ETOT  (EE + NN)
#define FDIM  128
#define HIDC  32
#define HEADS 4
#define GG    256
#define NEG   0.2f

// ---------------- scratch (device globals; referenced ONLY from device code) --------
static __device__ float g_hw[(size_t)NN * FDIM];    // GEMM output (pre-attention h, fp32)
static __device__ float g_feat[(size_t)NN * FDIM];  // aggregated + ELU output (layer input)
static __device__ float g_asrc[NN * HEADS];
static __device__ float g_adst[NN * HEADS];
static __device__ int   g_rowptr[NN + 1];
static __device__ int   g_cur[NN];
static __device__ int   g_col[ETOT];
static __device__ int   g_bsums[256];
static __device__ float g_pool[GG * HIDC];
static __device__ float g_pcnt[GG];
static __device__ __half g_wt1[128 * 128];  // W1^T [n][k] fp16
static __device__ __half g_wt2[128 * 128];  // W2^T
static __device__ __half g_wt3[32 * 128];   // W3^T

__device__ __forceinline__ float lrelu(float x) { return x > 0.f ? x : NEG * x; }
__device__ __forceinline__ float elu(float x)   { return x > 0.f ? x : expm1f(x); }
__device__ __forceinline__ int clampN(int v) { return v < 0 ? 0 : (v >= NN ? NN - 1 : v); }

static __host__ int cdiv(int a, int b) { return (a + b - 1) / b; }

// ---------------- CSR build ----------------
__global__ void k_init() {
    int i = blockIdx.x * blockDim.x + threadIdx.x;
    if (i < NN) g_cur[i] = 1;
    if (i < GG * HIDC) g_pool[i] = 0.f;
    if (i < GG) g_pcnt[i] = 0.f;
}

// transpose+convert all three weight matrices to half [n][k]
__global__ void k_cvtW(const float* __restrict__ W1, const float* __restrict__ W2,
                       const float* __restrict__ W3) {
    int id = blockIdx.x * blockDim.x + threadIdx.x;
    if (id < 128 * 128) {
        int n = id >> 7, k = id & 127;
        g_wt1[id] = __float2half(W1[k * 128 + n]);
        g_wt2[id] = __float2half(W2[k * 128 + n]);
        if (n < 32) g_wt3[n * 128 + k] = __float2half(W3[k * 32 + n]);
    }
}

__global__ void k_hist(const int* __restrict__ ei) {
    int e4 = blockIdx.x * blockDim.x + threadIdx.x;
    if (e4 * 4 < EE) {
        int4 d = *(const int4*)&ei[EE + e4 * 4];
        atomicAdd(&g_cur[clampN(d.x)], 1);
        atomicAdd(&g_cur[clampN(d.y)], 1);
        atomicAdd(&g_cur[clampN(d.z)], 1);
        atomicAdd(&g_cur[clampN(d.w)], 1);
    }
}

__global__ void k_scan1() {
    __shared__ int s[1024];
    int b = blockIdx.x, t = threadIdx.x;
    int i = b * 1024 + t;
    int v = (i < NN) ? g_cur[i] : 0;
    s[t] = v;
    __syncthreads();
    for (int off = 1; off < 1024; off <<= 1) {
        int x = (t >= off) ? s[t - off] : 0;
        __syncthreads();
        s[t] += x;
        __syncthreads();
    }
    if (i < NN) g_rowptr[i] = s[t] - v;
    if (t == 1023) g_bsums[b] = s[1023];
}

__global__ void k_scan2(int nb) {
    __shared__ int s[1024];
    int t = threadIdx.x;
    int v = (t < nb) ? g_bsums[t] : 0;
    s[t] = v;
    __syncthreads();
    for (int off = 1; off < 1024; off <<= 1) {
        int x = (t >= off) ? s[t - off] : 0;
        __syncthreads();
        s[t] += x;
        __syncthreads();
    }
    if (t < nb) g_bsums[t] = s[t] - v;
    if (t == 0) g_bsums[nb] = s[nb - 1];
}

__global__ void k_scan3cs(int nb) {
    int i = blockIdx.x * blockDim.x + threadIdx.x;
    if (i < NN) {
        int p = g_rowptr[i] + g_bsums[i >> 10];
        g_rowptr[i] = p;
        g_col[p] = i;
        g_cur[i] = p + 1;
    }
    if (i == 0) g_rowptr[NN] = g_bsums[nb];
}

__global__ void k_scatter(const int* __restrict__ ei) {
    int e4 = blockIdx.x * blockDim.x + threadIdx.x;
    if (e4 * 4 < EE) {
        int4 s = *(const int4*)&ei[e4 * 4];
        int4 d = *(const int4*)&ei[EE + e4 * 4];
        g_col[atomicAdd(&g_cur[clampN(d.x)], 1)] = clampN(s.x);
        g_col[atomicAdd(&g_cur[clampN(d.y)], 1)] = clampN(s.y);
        g_col[atomicAdd(&g_cur[clampN(d.z)], 1)] = clampN(s.z);
        g_col[atomicAdd(&g_cur[clampN(d.w)], 1)] = clampN(s.w);
    }
}

// ---------------- FP16 TC GEMM + fused attention-coef epilogue ----------------
__device__ __forceinline__ void mma_fp16(float* d, const uint32_t* a, const uint32_t* b,
                                         const float* c) {
    asm volatile(
        "mma.sync.aligned.m16n8k16.row.col.f32.f16.f16.f32 "
        "{%0,%1,%2,%3}, {%4,%5,%6,%7}, {%8,%9}, {%10,%11,%12,%13};\n"
        : "=f"(d[0]), "=f"(d[1]), "=f"(d[2]), "=f"(d[3])
        : "r"(a[0]), "r"(a[1]), "r"(a[2]), "r"(a[3]), "r"(b[0]), "r"(b[1]),
          "f"(c[0]), "f"(c[1]), "f"(c[2]), "f"(c[3]));
}

__device__ __forceinline__ void ldsm_x4(uint32_t& r0, uint32_t& r1, uint32_t& r2, uint32_t& r3,
                                        uint32_t addr) {
    asm volatile("ldmatrix.sync.aligned.m8n8.x4.shared.b16 {%0,%1,%2,%3}, [%4];"
                 : "=r"(r0), "=r"(r1), "=r"(r2), "=r"(r3)
                 : "r"(addr));
}

// 256 threads = 8 warps (4 in M x 2 in N). Block tile 128 x BN, K chunked by 32.
// Fragments via ldmatrix (conflict-free: row stride 80B covers all 32 banks per 8 rows).
template <int BN, bool FROMFEAT, bool COEF, int WSEL>
__global__ __launch_bounds__(256) void k_gemm_fp16(const float* __restrict__ Aex,
                                                   const float* __restrict__ a_s,
                                                   const float* __restrict__ a_d, int nrows) {
    constexpr int BK = 32;
    constexpr int ASTR = BK + 8;       // 40 halves (80B)
    constexpr int WTN = BN / 2;
    constexpr int NFRAG = WTN / 8;
    __shared__ __half As[128 * ASTR];
    __shared__ __half Bs[BN * ASTR];
    const float* A = FROMFEAT ? g_feat : Aex;
    const __half* WT = (WSEL == 1) ? g_wt1 : (WSEL == 2) ? g_wt2 : g_wt3;

    int t = threadIdx.x;
    int wid = t >> 5, lane = t & 31;
    int wm = wid & 3, wn = wid >> 2;
    int g = lane >> 2, tig = lane & 3;
    int rowBase = blockIdx.x * 128;

    uint32_t asBase = (uint32_t)__cvta_generic_to_shared(As);
    uint32_t bsBase = (uint32_t)__cvta_generic_to_shared(Bs);
    // ldmatrix per-lane row/col selectors
    int aRowSel = (lane & 7) + ((lane & 8) ? 8 : 0);     // within 16-row A block
    int aKSel   = (lane & 16) ? 8 : 0;
    int bRowSel = (lane & 7) + ((lane & 16) ? 8 : 0);    // within 16-row B block
    int bKSel   = (lane & 8) ? 8 : 0;

    float acc[2][NFRAG][4];
#pragma unroll
    for (int i = 0; i < 2; i++)
#pragma unroll
        for (int j = 0; j < NFRAG; j++)
#pragma unroll
            for (int k = 0; k < 4; k++) acc[i][j][k] = 0.f;

    float4 ra[4];
#pragma unroll
    for (int i = 0; i < 4; i++) {
        int f = t + i * 256;
        int r = f >> 3, c = (f & 7) * 4;
        int grow = rowBase + r;
        ra[i] = (grow < nrows) ? *(const float4*)&A[(size_t)grow * 128 + c]
                               : make_float4(0.f, 0.f, 0.f, 0.f);
    }

    for (int k0 = 0; k0 < 128; k0 += BK) {
        if (k0) __syncthreads();
        // A fill: float4 -> 2x half2 -> STS.64
#pragma unroll
        for (int i = 0; i < 4; i++) {
            int f = t + i * 256;
            int r = f >> 3, c = (f & 7) * 4;
            __half2 h01 = __floats2half2_rn(ra[i].x, ra[i].y);
            __half2 h23 = __floats2half2_rn(ra[i].z, ra[i].w);
            uint2 u;
            u.x = *(uint32_t*)&h01;
            u.y = *(uint32_t*)&h23;
            *(uint2*)&As[r * ASTR + c] = u;
        }
        // B fill from WT[n][k]
#pragma unroll
        for (int u = t; u < BN * 4; u += 256) {
            int n = u >> 2, part = u & 3;
            uint4 v = *(const uint4*)&WT[n * 128 + k0 + part * 8];
            *(uint4*)&Bs[n * ASTR + part * 8] = v;
        }
        __syncthreads();
        if (k0 + BK < 128) {  // prefetch next A chunk (overlaps MMA)
#pragma unroll
            for (int i = 0; i < 4; i++) {
                int f = t + i * 256;
                int r = f >> 3, c = (f & 7) * 4;
                int grow = rowBase + r;
                ra[i] = (grow < nrows) ? *(const float4*)&A[(size_t)grow * 128 + k0 + BK + c]
                                       : make_float4(0.f, 0.f, 0.f, 0.f);
            }
        }
#pragma unroll
        for (int kk = 0; kk < BK; kk += 16) {
            uint32_t af[2][4];
#pragma unroll
            for (int mf = 0; mf < 2; mf++) {
                int row = wm * 32 + mf * 16 + aRowSel;
                uint32_t addr = asBase + (uint32_t)(row * ASTR + kk + aKSel) * 2u;
                ldsm_x4(af[mf][0], af[mf][1], af[mf][2], af[mf][3], addr);
            }
#pragma unroll
            for (int nfp = 0; nfp < NFRAG / 2; nfp++) {
                int n0 = wn * WTN + nfp * 16;
                uint32_t addr = bsBase + (uint32_t)((n0 + bRowSel) * ASTR + kk + bKSel) * 2u;
                uint32_t r0, r1, r2, r3;
                ldsm_x4(r0, r1, r2, r3, addr);
                uint32_t bf0[2] = {r0, r1};
                uint32_t bf1[2] = {r2, r3};
#pragma unroll
                for (int mf = 0; mf < 2; mf++) {
                    mma_fp16(acc[mf][nfp * 2], af[mf], bf0, acc[mf][nfp * 2]);
                    mma_fp16(acc[mf][nfp * 2 + 1], af[mf], bf1, acc[mf][nfp * 2 + 1]);
                }
            }
        }
        __syncthreads();
    }

    // epilogue: fp32 store
#pragma unroll
    for (int mf = 0; mf < 2; mf++) {
        int r0 = rowBase + wm * 32 + mf * 16 + g;
#pragma unroll
        for (int nf = 0; nf < NFRAG; nf++) {
            int c = wn * WTN + nf * 8 + tig * 2;
            if (r0 < nrows)
                *(float2*)&g_hw[(size_t)r0 * BN + c] = make_float2(acc[mf][nf][0], acc[mf][nf][1]);
            if (r0 + 8 < nrows)
                *(float2*)&g_hw[(size_t)(r0 + 8) * BN + c] =
                    make_float2(acc[mf][nf][2], acc[mf][nf][3]);
        }
    }

    if (COEF && BN == 128) {
        int hbase = wn * 2;
        float asv[16], adv_[16];
#pragma unroll
        for (int nf = 0; nf < 8; nf++) {
            int c = wn * 64 + nf * 8 + tig * 2;
            int h = c >> 5, ch = c & 31;
            asv[nf * 2]      = __ldg(&a_s[h * 32 + ch]);
            asv[nf * 2 + 1]  = __ldg(&a_s[h * 32 + ch + 1]);
            adv_[nf * 2]     = __ldg(&a_d[h * 32 + ch]);
            adv_[nf * 2 + 1] = __ldg(&a_d[h * 32 + ch + 1]);
        }
#pragma unroll
        for (int mf = 0; mf < 2; mf++)
#pragma unroll
            for (int half = 0; half < 2; half++) {
                int v = rowBase + wm * 32 + mf * 16 + g + half * 8;
                float ps0 = 0.f, ps1 = 0.f, pd0 = 0.f, pd1 = 0.f;
#pragma unroll
                for (int nf = 0; nf < 8; nf++) {
                    float v0 = acc[mf][nf][half * 2 + 0];
                    float v1 = acc[mf][nf][half * 2 + 1];
                    if (nf < 4) {
                        ps0 = fmaf(v0, asv[nf * 2], fmaf(v1, asv[nf * 2 + 1], ps0));
                        pd0 = fmaf(v0, adv_[nf * 2], fmaf(v1, adv_[nf * 2 + 1], pd0));
                    } else {
                        ps1 = fmaf(v0, asv[nf * 2], fmaf(v1, asv[nf * 2 + 1], ps1));
                        pd1 = fmaf(v0, adv_[nf * 2], fmaf(v1, adv_[nf * 2 + 1], pd1));
                    }
                }
                ps0 += __shfl_down_sync(0xffffffffu, ps0, 1);
                ps0 += __shfl_down_sync(0xffffffffu, ps0, 2);
                ps1 += __shfl_down_sync(0xffffffffu, ps1, 1);
                ps1 += __shfl_down_sync(0xffffffffu, ps1, 2);
                pd0 += __shfl_down_sync(0xffffffffu, pd0, 1);
                pd0 += __shfl_down_sync(0xffffffffu, pd0, 2);
                pd1 += __shfl_down_sync(0xffffffffu, pd1, 1);
                pd1 += __shfl_down_sync(0xffffffffu, pd1, 2);
                if (tig == 0 && v < nrows) {
                    g_asrc[v * 4 + hbase]     = ps0;
                    g_asrc[v * 4 + hbase + 1] = ps1;
                    g_adst[v * 4 + hbase]     = pd0;
                    g_adst[v * 4 + hbase + 1] = pd1;
                }
            }
    }
}

// ---------------- layer-3 attention coefficients (1 head) ----------------
__global__ void k_coef1(const float* __restrict__ a_s, const float* __restrict__ a_d) {
    int v = blockIdx.x * 8 + (threadIdx.x >> 5);
    int l = threadIdx.x & 31;
    if (v >= NN) return;
    float hv = g_hw[(size_t)v * 32 + l];
    float ps = hv * a_s[l];
    float pd = hv * a_d[l];
    for (int off = 16; off; off >>= 1) {
        ps += __shfl_xor_sync(0xffffffffu, ps, off);
        pd += __shfl_xor_sync(0xffffffffu, pd, off);
    }
    if (l == 0) {
        g_asrc[v] = ps;
        g_adst[v] = pd;
    }
}

// ---------------- fused softmax + aggregation, 4 heads (warp per dst) ----------------
__global__ void k_gat4(const float* __restrict__ bias) {
    int v = blockIdx.x * 8 + (threadIdx.x >> 5);
    int l = threadIdx.x & 31;
    if (v >= NN) return;
    int beg = g_rowptr[v], end = g_rowptr[v + 1];
    float4 adv = *(const float4*)&g_adst[v * 4];

    int hq = l & 3;
    int ha = l >> 3;
    float adh = (hq == 0) ? adv.x : (hq == 1) ? adv.y : (hq == 2) ? adv.z : adv.w;

    float den = 0.f;
    uint64_t acc01 = 0ull, acc23 = 0ull;
    for (int base = beg; base < end; base += 8) {
        int i = base + (l >> 2);
        float ex = 0.f;
        int s = 0;
        if (i < end) {
            s = g_col[i];
            float a = __ldg(&g_asrc[s * 4 + hq]);
            ex = __expf(lrelu(a + adh));
        }
        den += ex;
        int lim = min(8, end - base);
#pragma unroll 8
        for (int j = 0; j < lim; j++) {
            float exj = __shfl_sync(0xffffffffu, ex, j * 4 + ha);
            int sj = __shfl_sync(0xffffffffu, s, j * 4);
            float4 hv = __ldg((const float4*)&g_hw[(size_t)sj * 128 + l * 4]);
            uint64_t e2, h01, h23;
            asm("mov.b64 %0, {%1, %1};" : "=l"(e2) : "f"(exj));
            asm("mov.b64 %0, {%1, %2};" : "=l"(h01) : "f"(hv.x), "f"(hv.y));
            asm("mov.b64 %0, {%1, %2};" : "=l"(h23) : "f"(hv.z), "f"(hv.w));
            asm("fma.rn.f32x2 %0, %1, %2, %0;" : "+l"(acc01) : "l"(h01), "l"(e2));
            asm("fma.rn.f32x2 %0, %1, %2, %0;" : "+l"(acc23) : "l"(h23), "l"(e2));
        }
    }
    den += __shfl_xor_sync(0xffffffffu, den, 4);
    den += __shfl_xor_sync(0xffffffffu, den, 8);
    den += __shfl_xor_sync(0xffffffffu, den, 16);
    float dm = __shfl_sync(0xffffffffu, den, ha);
    float inv = 1.f / (dm + 1e-16f);
    float ax, ay, az, aw;
    asm("mov.b64 {%0, %1}, %2;" : "=f"(ax), "=f"(ay) : "l"(acc01));
    asm("mov.b64 {%0, %1}, %2;" : "=f"(az), "=f"(aw) : "l"(acc23));
    float4 b = *(const float4*)&bias[l * 4];
    float4 o;
    o.x = elu(ax * inv + b.x);
    o.y = elu(ay * inv + b.y);
    o.z = elu(az * inv + b.z);
    o.w = elu(aw * inv + b.w);
    *(float4*)&g_feat[(size_t)v * 128 + l * 4] = o;
}

// ---------------- fused softmax + aggregation + POOL, 1 head / 32 ch ----------------
// Final layer: output feeds only the mean-pool, so atomically accumulate directly.
__global__ void k_gat1(const float* __restrict__ bias, const int* __restrict__ batch) {
    int v = blockIdx.x * 8 + (threadIdx.x >> 5);
    int l = threadIdx.x & 31;
    if (v >= NN) return;
    int beg = g_rowptr[v], end = g_rowptr[v + 1];
    float adv = g_adst[v];

    float den = 0.f, acc = 0.f;
    for (int base = beg; base < end; base += 32) {
        int i = base + l;
        float ex = 0.f;
        int s = 0;
        if (i < end) {
            s = g_col[i];
            ex = __expf(lrelu(__ldg(&g_asrc[s]) + adv));
        }
        den += ex;
        int lim = min(32, end - base);
        for (int j = 0; j < lim; j++) {
            float exj = __shfl_sync(0xffffffffu, ex, j);
            int sj = __shfl_sync(0xffffffffu, s, j);
            acc = fmaf(exj, __ldg(&g_hw[(size_t)sj * 32 + l]), acc);
        }
    }
    for (int off = 16; off; off >>= 1)
        den += __shfl_xor_sync(0xffffffffu, den, off);
    float o = elu(acc / (den + 1e-16f) + bias[l]);
    int b = batch[v] & (GG - 1);
    atomicAdd(&g_pool[b * 32 + l], o);
    if (l == 0) atomicAdd(&g_pcnt[b], 1.f);
}

__global__ void k_readout(const float* __restrict__ fc_w, const float* __restrict__ fc_b,
                          float* __restrict__ out) {
    int g = blockIdx.x * 8 + (threadIdx.x >> 5);
    int l = threadIdx.x & 31;
    if (g >= GG) return;
    float v = g_pool[g * 32 + l] * fc_w[l];
    for (int off = 16; off; off >>= 1)
        v += __shfl_xor_sync(0xffffffffu, v, off);
    if (l == 0) {
        float c = fmaxf(g_pcnt[g], 1.f);
        out[g] = v / c + fc_b[0];
    }
}

// ---------------- launch ----------------
extern "C" void kernel_launch(void* const* d_in, const int* in_sizes, int n_in,
                              void* d_out, int out_size) {
    const float* x      = (const float*)d_in[0];
    const int*   ei     = (const int*)d_in[1];
    const int*   batch  = (const int*)d_in[2];
    const float* W1     = (const float*)d_in[3];
    const float* a_src1 = (const float*)d_in[4];
    const float* a_dst1 = (const float*)d_in[5];
    const float* b1     = (const float*)d_in[6];
    const float* W2     = (const float*)d_in[7];
    const float* a_src2 = (const float*)d_in[8];
    const float* a_dst2 = (const float*)d_in[9];
    const float* b2     = (const float*)d_in[10];
    const float* W3     = (const float*)d_in[11];
    const float* a_src3 = (const float*)d_in[12];
    const float* a_dst3 = (const float*)d_in[13];
    const float* b3     = (const float*)d_in[14];
    const float* fc_w   = (const float*)d_in[15];
    const float* fc_b   = (const float*)d_in[16];
    float* out = (float*)d_out;

    const int T = 256;
    const int nb = cdiv(NN, 1024);  // 98
    int gGrid = cdiv(NN, 128);
    int wGrid = cdiv(NN, 8);

    // 15 launches; layer-1 GEMM kept at slot #4 (ncu capture target).
    k_init<<<cdiv(NN, T), T>>>();
    k_hist<<<cdiv(EE / 4, T), T>>>(ei);
    k_cvtW<<<cdiv(128 * 128, T), T>>>(W1, W2, W3);
    k_gemm_fp16<128, false, true, 1><<<gGrid, 256>>>(x, a_src1, a_dst1, NN);  // #4
    k_scan1<<<nb, 1024>>>();
    k_scan2<<<1, 1024>>>(nb);
    k_scan3cs<<<cdiv(NN, T), T>>>(nb);
    k_scatter<<<cdiv(EE / 4, T), T>>>(ei);

    k_gat4<<<wGrid, T>>>(b1);

    k_gemm_fp16<128, true, true, 2><<<gGrid, 256>>>(nullptr, a_src2, a_dst2, NN);
    k_gat4<<<wGrid, T>>>(b2);

    k_gemm_fp16<32, true, false, 3><<<gGrid, 256>>>(nullptr, nullptr, nullptr, NN);
    k_coef1<<<wGrid, T>>>(a_src3, a_dst3);
    k_gat1<<<wGrid, T>>>(b3, batch);

    k_readout<<<cdiv(GG, 8), T>>>(fc_w, fc_b, out);
}

// round 17
// speedup vs baseline: 1.1143x; 1.1143x over previous
#include <cuda_runtime.h>
#include <cuda_fp16.h>
#include <cstdint>

#define NN    100000
#define EE    1600000
#define ETOT  (EE + NN)
#define FDIM  128
#define HIDC  32
#define HEADS 4
#define GG    256
#define NEG   0.2f

// ---------------- scratch (device globals; referenced ONLY from device code) --------
static __device__ float g_hw[(size_t)NN * FDIM];    // GEMM output (pre-attention h, fp32)
static __device__ float g_feat[(size_t)NN * FDIM];  // aggregated + ELU output (layer input)
static __device__ float g_asrc[NN * HEADS];
static __device__ float g_adst[NN * HEADS];
static __device__ int   g_rowptr[NN + 1];
static __device__ int   g_cur[NN];
static __device__ int   g_col[ETOT];
static __device__ int   g_bsums[256];
static __device__ float g_pool[GG * HIDC];
static __device__ float g_pcnt[GG];
static __device__ __half g_wt1[128 * 128];  // W1^T [n][k] fp16
static __device__ __half g_wt2[128 * 128];  // W2^T
static __device__ __half g_wt3[32 * 128];   // W3^T

__device__ __forceinline__ float lrelu(float x) { return x > 0.f ? x : NEG * x; }
__device__ __forceinline__ float elu(float x)   { return x > 0.f ? x : expm1f(x); }
__device__ __forceinline__ int clampN(int v) { return v < 0 ? 0 : (v >= NN ? NN - 1 : v); }

static __host__ int cdiv(int a, int b) { return (a + b - 1) / b; }

// ---------------- init + weight transpose/convert (merged) ----------------
__global__ void k_initW(const float* __restrict__ W1, const float* __restrict__ W2,
                        const float* __restrict__ W3) {
    int i = blockIdx.x * blockDim.x + threadIdx.x;
    if (i < NN) g_cur[i] = 1;
    if (i < GG * HIDC) g_pool[i] = 0.f;
    if (i < GG) g_pcnt[i] = 0.f;
    if (i < 128 * 128) {
        int n = i >> 7, k = i & 127;
        g_wt1[i] = __float2half(W1[k * 128 + n]);
        g_wt2[i] = __float2half(W2[k * 128 + n]);
        if (n < 32) g_wt3[n * 128 + k] = __float2half(W3[k * 32 + n]);
    }
}

__global__ void k_hist(const int* __restrict__ ei) {
    int e4 = blockIdx.x * blockDim.x + threadIdx.x;
    if (e4 * 4 < EE) {
        int4 d = *(const int4*)&ei[EE + e4 * 4];
        atomicAdd(&g_cur[clampN(d.x)], 1);
        atomicAdd(&g_cur[clampN(d.y)], 1);
        atomicAdd(&g_cur[clampN(d.z)], 1);
        atomicAdd(&g_cur[clampN(d.w)], 1);
    }
}

__global__ void k_scan1() {
    __shared__ int s[1024];
    int b = blockIdx.x, t = threadIdx.x;
    int i = b * 1024 + t;
    int v = (i < NN) ? g_cur[i] : 0;
    s[t] = v;
    __syncthreads();
    for (int off = 1; off < 1024; off <<= 1) {
        int x = (t >= off) ? s[t - off] : 0;
        __syncthreads();
        s[t] += x;
        __syncthreads();
    }
    if (i < NN) g_rowptr[i] = s[t] - v;
    if (t == 1023) g_bsums[b] = s[1023];
}

__global__ void k_scan2(int nb) {
    __shared__ int s[1024];
    int t = threadIdx.x;
    int v = (t < nb) ? g_bsums[t] : 0;
    s[t] = v;
    __syncthreads();
    for (int off = 1; off < 1024; off <<= 1) {
        int x = (t >= off) ? s[t - off] : 0;
        __syncthreads();
        s[t] += x;
        __syncthreads();
    }
    if (t < nb) g_bsums[t] = s[t] - v;
    if (t == 0) g_bsums[nb] = s[nb - 1];
}

__global__ void k_scan3cs(int nb) {
    int i = blockIdx.x * blockDim.x + threadIdx.x;
    if (i < NN) {
        int p = g_rowptr[i] + g_bsums[i >> 10];
        g_rowptr[i] = p;
        g_col[p] = i;
        g_cur[i] = p + 1;
    }
    if (i == 0) g_rowptr[NN] = g_bsums[nb];
}

__global__ void k_scatter(const int* __restrict__ ei) {
    int e4 = blockIdx.x * blockDim.x + threadIdx.x;
    if (e4 * 4 < EE) {
        int4 s = *(const int4*)&ei[e4 * 4];
        int4 d = *(const int4*)&ei[EE + e4 * 4];
        g_col[atomicAdd(&g_cur[clampN(d.x)], 1)] = clampN(s.x);
        g_col[atomicAdd(&g_cur[clampN(d.y)], 1)] = clampN(s.y);
        g_col[atomicAdd(&g_cur[clampN(d.z)], 1)] = clampN(s.z);
        g_col[atomicAdd(&g_cur[clampN(d.w)], 1)] = clampN(s.w);
    }
}

// ---------------- FP16 TC GEMM + fused attention-coef epilogues ----------------
__device__ __forceinline__ void mma_fp16(float* d, const uint32_t* a, const uint32_t* b,
                                         const float* c) {
    asm volatile(
        "mma.sync.aligned.m16n8k16.row.col.f32.f16.f16.f32 "
        "{%0,%1,%2,%3}, {%4,%5,%6,%7}, {%8,%9}, {%10,%11,%12,%13};\n"
        : "=f"(d[0]), "=f"(d[1]), "=f"(d[2]), "=f"(d[3])
        : "r"(a[0]), "r"(a[1]), "r"(a[2]), "r"(a[3]), "r"(b[0]), "r"(b[1]),
          "f"(c[0]), "f"(c[1]), "f"(c[2]), "f"(c[3]));
}

__device__ __forceinline__ void ldsm_x4(uint32_t& r0, uint32_t& r1, uint32_t& r2, uint32_t& r3,
                                        uint32_t addr) {
    asm volatile("ldmatrix.sync.aligned.m8n8.x4.shared.b16 {%0,%1,%2,%3}, [%4];"
                 : "=r"(r0), "=r"(r1), "=r"(r2), "=r"(r3)
                 : "r"(addr));
}

// 256 threads = 8 warps (4 in M x 2 in N). Block tile 128 x BN, K chunked by 32.
// COEF: BN==128 -> fused 4-head coef epilogue (per-warp disjoint heads).
//       BN==32  -> fused 1-head coef epilogue (cross-warp smem combine).
template <int BN, bool FROMFEAT, bool COEF, int WSEL>
__global__ __launch_bounds__(256) void k_gemm_fp16(const float* __restrict__ Aex,
                                                   const float* __restrict__ a_s,
                                                   const float* __restrict__ a_d, int nrows) {
    constexpr int BK = 32;
    constexpr int ASTR = BK + 8;       // 40 halves (80B)
    constexpr int WTN = BN / 2;
    constexpr int NFRAG = WTN / 8;
    __shared__ __half As[128 * ASTR];
    __shared__ __half Bs[BN * ASTR];
    __shared__ float sred[2][2][128];  // [wn][s/d][row] for BN==32 coef combine
    const float* A = FROMFEAT ? g_feat : Aex;
    const __half* WT = (WSEL == 1) ? g_wt1 : (WSEL == 2) ? g_wt2 : g_wt3;

    int t = threadIdx.x;
    int wid = t >> 5, lane = t & 31;
    int wm = wid & 3, wn = wid >> 2;
    int g = lane >> 2, tig = lane & 3;
    int rowBase = blockIdx.x * 128;

    uint32_t asBase = (uint32_t)__cvta_generic_to_shared(As);
    uint32_t bsBase = (uint32_t)__cvta_generic_to_shared(Bs);
    int aRowSel = (lane & 7) + ((lane & 8) ? 8 : 0);
    int aKSel   = (lane & 16) ? 8 : 0;
    int bRowSel = (lane & 7) + ((lane & 16) ? 8 : 0);
    int bKSel   = (lane & 8) ? 8 : 0;

    float acc[2][NFRAG][4];
#pragma unroll
    for (int i = 0; i < 2; i++)
#pragma unroll
        for (int j = 0; j < NFRAG; j++)
#pragma unroll
            for (int k = 0; k < 4; k++) acc[i][j][k] = 0.f;

    float4 ra[4];
#pragma unroll
    for (int i = 0; i < 4; i++) {
        int f = t + i * 256;
        int r = f >> 3, c = (f & 7) * 4;
        int grow = rowBase + r;
        ra[i] = (grow < nrows) ? *(const float4*)&A[(size_t)grow * 128 + c]
                               : make_float4(0.f, 0.f, 0.f, 0.f);
    }

    for (int k0 = 0; k0 < 128; k0 += BK) {
        if (k0) __syncthreads();
#pragma unroll
        for (int i = 0; i < 4; i++) {
            int f = t + i * 256;
            int r = f >> 3, c = (f & 7) * 4;
            __half2 h01 = __floats2half2_rn(ra[i].x, ra[i].y);
            __half2 h23 = __floats2half2_rn(ra[i].z, ra[i].w);
            uint2 u;
            u.x = *(uint32_t*)&h01;
            u.y = *(uint32_t*)&h23;
            *(uint2*)&As[r * ASTR + c] = u;
        }
#pragma unroll
        for (int u = t; u < BN * 4; u += 256) {
            int n = u >> 2, part = u & 3;
            uint4 v = *(const uint4*)&WT[n * 128 + k0 + part * 8];
            *(uint4*)&Bs[n * ASTR + part * 8] = v;
        }
        __syncthreads();
        if (k0 + BK < 128) {
#pragma unroll
            for (int i = 0; i < 4; i++) {
                int f = t + i * 256;
                int r = f >> 3, c = (f & 7) * 4;
                int grow = rowBase + r;
                ra[i] = (grow < nrows) ? *(const float4*)&A[(size_t)grow * 128 + k0 + BK + c]
                                       : make_float4(0.f, 0.f, 0.f, 0.f);
            }
        }
#pragma unroll
        for (int kk = 0; kk < BK; kk += 16) {
            uint32_t af[2][4];
#pragma unroll
            for (int mf = 0; mf < 2; mf++) {
                int row = wm * 32 + mf * 16 + aRowSel;
                uint32_t addr = asBase + (uint32_t)(row * ASTR + kk + aKSel) * 2u;
                ldsm_x4(af[mf][0], af[mf][1], af[mf][2], af[mf][3], addr);
            }
#pragma unroll
            for (int nfp = 0; nfp < NFRAG / 2; nfp++) {
                int n0 = wn * WTN + nfp * 16;
                uint32_t addr = bsBase + (uint32_t)((n0 + bRowSel) * ASTR + kk + bKSel) * 2u;
                uint32_t r0, r1, r2, r3;
                ldsm_x4(r0, r1, r2, r3, addr);
                uint32_t bf0[2] = {r0, r1};
                uint32_t bf1[2] = {r2, r3};
#pragma unroll
                for (int mf = 0; mf < 2; mf++) {
                    mma_fp16(acc[mf][nfp * 2], af[mf], bf0, acc[mf][nfp * 2]);
                    mma_fp16(acc[mf][nfp * 2 + 1], af[mf], bf1, acc[mf][nfp * 2 + 1]);
                }
            }
        }
        __syncthreads();
    }

    // epilogue: fp32 store
#pragma unroll
    for (int mf = 0; mf < 2; mf++) {
        int r0 = rowBase + wm * 32 + mf * 16 + g;
#pragma unroll
        for (int nf = 0; nf < NFRAG; nf++) {
            int c = wn * WTN + nf * 8 + tig * 2;
            if (r0 < nrows)
                *(float2*)&g_hw[(size_t)r0 * BN + c] = make_float2(acc[mf][nf][0], acc[mf][nf][1]);
            if (r0 + 8 < nrows)
                *(float2*)&g_hw[(size_t)(r0 + 8) * BN + c] =
                    make_float2(acc[mf][nf][2], acc[mf][nf][3]);
        }
    }

    if (COEF && BN == 128) {
        int hbase = wn * 2;
        float asv[16], adv_[16];
#pragma unroll
        for (int nf = 0; nf < 8; nf++) {
            int c = wn * 64 + nf * 8 + tig * 2;
            int h = c >> 5, ch = c & 31;
            asv[nf * 2]      = __ldg(&a_s[h * 32 + ch]);
            asv[nf * 2 + 1]  = __ldg(&a_s[h * 32 + ch + 1]);
            adv_[nf * 2]     = __ldg(&a_d[h * 32 + ch]);
            adv_[nf * 2 + 1] = __ldg(&a_d[h * 32 + ch + 1]);
        }
#pragma unroll
        for (int mf = 0; mf < 2; mf++)
#pragma unroll
            for (int half = 0; half < 2; half++) {
                int v = rowBase + wm * 32 + mf * 16 + g + half * 8;
                float ps0 = 0.f, ps1 = 0.f, pd0 = 0.f, pd1 = 0.f;
#pragma unroll
                for (int nf = 0; nf < 8; nf++) {
                    float v0 = acc[mf][nf][half * 2 + 0];
                    float v1 = acc[mf][nf][half * 2 + 1];
                    if (nf < 4) {
                        ps0 = fmaf(v0, asv[nf * 2], fmaf(v1, asv[nf * 2 + 1], ps0));
                        pd0 = fmaf(v0, adv_[nf * 2], fmaf(v1, adv_[nf * 2 + 1], pd0));
                    } else {
                        ps1 = fmaf(v0, asv[nf * 2], fmaf(v1, asv[nf * 2 + 1], ps1));
                        pd1 = fmaf(v0, adv_[nf * 2], fmaf(v1, adv_[nf * 2 + 1], pd1));
                    }
                }
                ps0 += __shfl_down_sync(0xffffffffu, ps0, 1);
                ps0 += __shfl_down_sync(0xffffffffu, ps0, 2);
                ps1 += __shfl_down_sync(0xffffffffu, ps1, 1);
                ps1 += __shfl_down_sync(0xffffffffu, ps1, 2);
                pd0 += __shfl_down_sync(0xffffffffu, pd0, 1);
                pd0 += __shfl_down_sync(0xffffffffu, pd0, 2);
                pd1 += __shfl_down_sync(0xffffffffu, pd1, 1);
                pd1 += __shfl_down_sync(0xffffffffu, pd1, 2);
                if (tig == 0 && v < nrows) {
                    g_asrc[v * 4 + hbase]     = ps0;
                    g_asrc[v * 4 + hbase + 1] = ps1;
                    g_adst[v * 4 + hbase]     = pd0;
                    g_adst[v * 4 + hbase + 1] = pd1;
                }
            }
    }

    if (COEF && BN == 32) {
        // 1-head coef: each thread covers 4 cols; quad-reduce, then combine wn halves.
        float as_c[4], ad_c[4];
#pragma unroll
        for (int nf = 0; nf < 2; nf++)
#pragma unroll
            for (int sub = 0; sub < 2; sub++) {
                int c = wn * 16 + nf * 8 + tig * 2 + sub;
                as_c[nf * 2 + sub] = __ldg(&a_s[c]);
                ad_c[nf * 2 + sub] = __ldg(&a_d[c]);
            }
#pragma unroll
        for (int mf = 0; mf < 2; mf++)
#pragma unroll
            for (int half = 0; half < 2; half++) {
                int rloc = wm * 32 + mf * 16 + g + half * 8;
                float ps = 0.f, pd = 0.f;
#pragma unroll
                for (int nf = 0; nf < 2; nf++) {
                    ps = fmaf(acc[mf][nf][half * 2 + 0], as_c[nf * 2 + 0],
                              fmaf(acc[mf][nf][half * 2 + 1], as_c[nf * 2 + 1], ps));
                    pd = fmaf(acc[mf][nf][half * 2 + 0], ad_c[nf * 2 + 0],
                              fmaf(acc[mf][nf][half * 2 + 1], ad_c[nf * 2 + 1], pd));
                }
                ps += __shfl_down_sync(0xffffffffu, ps, 1);
                ps += __shfl_down_sync(0xffffffffu, ps, 2);
                pd += __shfl_down_sync(0xffffffffu, pd, 1);
                pd += __shfl_down_sync(0xffffffffu, pd, 2);
                if (tig == 0) {
                    sred[wn][0][rloc] = ps;
                    sred[wn][1][rloc] = pd;
                }
            }
        __syncthreads();
        if (t < 128) {
            int v = rowBase + t;
            if (v < nrows) {
                g_asrc[v] = sred[0][0][t] + sred[1][0][t];
                g_adst[v] = sred[0][1][t] + sred[1][1][t];
            }
        }
    }
}

// ---------------- fused softmax + aggregation, 4 heads (warp per dst) ----------------
__global__ void k_gat4(const float* __restrict__ bias) {
    int v = blockIdx.x * 8 + (threadIdx.x >> 5);
    int l = threadIdx.x & 31;
    if (v >= NN) return;
    int beg = g_rowptr[v], end = g_rowptr[v + 1];
    float4 adv = *(const float4*)&g_adst[v * 4];

    int hq = l & 3;
    int ha = l >> 3;
    float adh = (hq == 0) ? adv.x : (hq == 1) ? adv.y : (hq == 2) ? adv.z : adv.w;

    float den = 0.f;
    uint64_t acc01 = 0ull, acc23 = 0ull;
    for (int base = beg; base < end; base += 8) {
        int i = base + (l >> 2);
        float ex = 0.f;
        int s = 0;
        if (i < end) {
            s = g_col[i];
            float a = __ldg(&g_asrc[s * 4 + hq]);
            ex = __expf(lrelu(a + adh));
        }
        den += ex;
        int lim = min(8, end - base);
#pragma unroll 8
        for (int j = 0; j < lim; j++) {
            float exj = __shfl_sync(0xffffffffu, ex, j * 4 + ha);
            int sj = __shfl_sync(0xffffffffu, s, j * 4);
            float4 hv = __ldg((const float4*)&g_hw[(size_t)sj * 128 + l * 4]);
            uint64_t e2, h01, h23;
            asm("mov.b64 %0, {%1, %1};" : "=l"(e2) : "f"(exj));
            asm("mov.b64 %0, {%1, %2};" : "=l"(h01) : "f"(hv.x), "f"(hv.y));
            asm("mov.b64 %0, {%1, %2};" : "=l"(h23) : "f"(hv.z), "f"(hv.w));
            asm("fma.rn.f32x2 %0, %1, %2, %0;" : "+l"(acc01) : "l"(h01), "l"(e2));
            asm("fma.rn.f32x2 %0, %1, %2, %0;" : "+l"(acc23) : "l"(h23), "l"(e2));
        }
    }
    den += __shfl_xor_sync(0xffffffffu, den, 4);
    den += __shfl_xor_sync(0xffffffffu, den, 8);
    den += __shfl_xor_sync(0xffffffffu, den, 16);
    float dm = __shfl_sync(0xffffffffu, den, ha);
    float inv = 1.f / (dm + 1e-16f);
    float ax, ay, az, aw;
    asm("mov.b64 {%0, %1}, %2;" : "=f"(ax), "=f"(ay) : "l"(acc01));
    asm("mov.b64 {%0, %1}, %2;" : "=f"(az), "=f"(aw) : "l"(acc23));
    float4 b = *(const float4*)&bias[l * 4];
    float4 o;
    o.x = elu(ax * inv + b.x);
    o.y = elu(ay * inv + b.y);
    o.z = elu(az * inv + b.z);
    o.w = elu(aw * inv + b.w);
    *(float4*)&g_feat[(size_t)v * 128 + l * 4] = o;
}

// ---------------- fused softmax + aggregation, 1 head / 32 ch ----------------
__global__ void k_gat1(const float* __restrict__ bias) {
    int v = blockIdx.x * 8 + (threadIdx.x >> 5);
    int l = threadIdx.x & 31;
    if (v >= NN) return;
    int beg = g_rowptr[v], end = g_rowptr[v + 1];
    float adv = g_adst[v];

    float den = 0.f, acc = 0.f;
    for (int base = beg; base < end; base += 32) {
        int i = base + l;
        float ex = 0.f;
        int s = 0;
        if (i < end) {
            s = g_col[i];
            ex = __expf(lrelu(__ldg(&g_asrc[s]) + adv));
        }
        den += ex;
        int lim = min(32, end - base);
        for (int j = 0; j < lim; j++) {
            float exj = __shfl_sync(0xffffffffu, ex, j);
            int sj = __shfl_sync(0xffffffffu, s, j);
            acc = fmaf(exj, __ldg(&g_hw[(size_t)sj * 32 + l]), acc);
        }
    }
    for (int off = 16; off; off >>= 1)
        den += __shfl_xor_sync(0xffffffffu, den, off);
    g_feat[(size_t)v * 32 + l] = elu(acc / (den + 1e-16f) + bias[l]);
}

// ---------------- pooling (run-length, sorted batch) + readout ----------------
__global__ void k_pool(const int* __restrict__ batch) {
    int w = blockIdx.x * (blockDim.x >> 5) + (threadIdx.x >> 5);
    int l = threadIdx.x & 31;
    int n0 = w * 4;
    if (n0 >= NN) return;
    int curb = batch[n0] & (GG - 1);
    float acc = 0.f;
    int cnt = 0;
#pragma unroll
    for (int k = 0; k < 4; k++) {
        int n = n0 + k;
        if (n >= NN) break;
        int b = batch[n] & (GG - 1);
        if (b != curb) {
            atomicAdd(&g_pool[curb * 32 + l], acc);
            if (l == 0) atomicAdd(&g_pcnt[curb], (float)cnt);
            acc = 0.f;
            cnt = 0;
            curb = b;
        }
        acc += g_feat[(size_t)n * 32 + l];
        cnt++;
    }
    atomicAdd(&g_pool[curb * 32 + l], acc);
    if (l == 0) atomicAdd(&g_pcnt[curb], (float)cnt);
}

__global__ void k_readout(const float* __restrict__ fc_w, const float* __restrict__ fc_b,
                          float* __restrict__ out) {
    int g = blockIdx.x * 8 + (threadIdx.x >> 5);
    int l = threadIdx.x & 31;
    if (g >= GG) return;
    float v = g_pool[g * 32 + l] * fc_w[l];
    for (int off = 16; off; off >>= 1)
        v += __shfl_xor_sync(0xffffffffu, v, off);
    if (l == 0) {
        float c = fmaxf(g_pcnt[g], 1.f);
        out[g] = v / c + fc_b[0];
    }
}

// ---------------- launch ----------------
extern "C" void kernel_launch(void* const* d_in, const int* in_sizes, int n_in,
                              void* d_out, int out_size) {
    const float* x      = (const float*)d_in[0];
    const int*   ei     = (const int*)d_in[1];
    const int*   batch  = (const int*)d_in[2];
    const float* W1     = (const float*)d_in[3];
    const float* a_src1 = (const float*)d_in[4];
    const float* a_dst1 = (const float*)d_in[5];
    const float* b1     = (const float*)d_in[6];
    const float* W2     = (const float*)d_in[7];
    const float* a_src2 = (const float*)d_in[8];
    const float* a_dst2 = (const float*)d_in[9];
    const float* b2     = (const float*)d_in[10];
    const float* W3     = (const float*)d_in[11];
    const float* a_src3 = (const float*)d_in[12];
    const float* a_dst3 = (const float*)d_in[13];
    const float* b3     = (const float*)d_in[14];
    const float* fc_w   = (const float*)d_in[15];
    const float* fc_b   = (const float*)d_in[16];
    float* out = (float*)d_out;

    const int T = 256;
    const int nb = cdiv(NN, 1024);  // 98
    int gGrid = cdiv(NN, 128);
    int wGrid = cdiv(NN, 8);

    // 14 launches; layer-1 GEMM kept at slot #4 (ncu capture target).
    k_initW<<<cdiv(NN, T), T>>>(W1, W2, W3);
    k_hist<<<cdiv(EE / 4, T), T>>>(ei);
    k_scan1<<<nb, 1024>>>();
    k_gemm_fp16<128, false, true, 1><<<gGrid, 256>>>(x, a_src1, a_dst1, NN);  // #4
    k_scan2<<<1, 1024>>>(nb);
    k_scan3cs<<<cdiv(NN, T), T>>>(nb);
    k_scatter<<<cdiv(EE / 4, T), T>>>(ei);

    k_gat4<<<wGrid, T>>>(b1);

    k_gemm_fp16<128, true, true, 2><<<gGrid, 256>>>(nullptr, a_src2, a_dst2, NN);
    k_gat4<<<wGrid, T>>>(b2);

    k_gemm_fp16<32, true, true, 3><<<gGrid, 256>>>(nullptr, a_src3, a_dst3, NN);
    k_gat1<<<wGrid, T>>>(b3);

    k_pool<<<cdiv(NN / 4, 8) + 1, T>>>(batch);
    k_readout<<<cdiv(GG, 8), T>>>(fc_w, fc_b, out);
}